// round 3
// baseline (speedup 1.0000x reference)
#include <cuda_runtime.h>

// Problem constants (fixed shapes from reference)
#define BATCH 8
#define TLEN  4096
#define BC    256
#define RC    64
#define NB0   4
#define NB1   3
#define TB    7           // NB0 + NB1
#define CH0   1024        // x0 channels
#define CH1   768         // x1 channels

#define GAP_GRID (BATCH * BC)          // 2048
#define PF_BLOCKS 17                   // prefetch CTAs at tail of gap grid

// Device-global scratch (allocation-free per harness rules)
__device__ float g_gap[BATCH * BC];
__device__ float g_att[BATCH * TB * BC];

// ---------------------------------------------------------------------------
// Kernel 1: block-sum over channel blocks + global average pool over time.
// grid = 2048 blocks, 256 threads. Streaming (evict-first) loads.
// The last 17 CTAs (scheduled in wave 2, i.e. late in the kernel) additionally
// prefetch the attention weights (Wh 448KB, W1 64KB, bh 7KB) into L2 so the
// downstream tiny kernels hit L2 instead of cold DRAM.
// ---------------------------------------------------------------------------
__global__ void __launch_bounds__(256) gap_kernel(const float* __restrict__ x0,
                                                  const float* __restrict__ x1,
                                                  const float* __restrict__ Wh,
                                                  const float* __restrict__ W1,
                                                  const float* __restrict__ bh) {
    const int b = blockIdx.x >> 8;      // / BC
    const int c = blockIdx.x & (BC - 1);
    const int tid = threadIdx.x;

    // --- L2 weight prefetch from late-wave CTAs ---
    if (blockIdx.x >= GAP_GRID - PF_BLOCKS) {
        const int pb = blockIdx.x - (GAP_GRID - PF_BLOCKS);   // 0..16
        if (pb < 14) {
            // Wh: 7*64*256*4 = 458752 B = 3584 lines of 128B; 14 blocks * 256 thr
            const int line = pb * 256 + tid;
            if (line < 3584) {
                const char* p = (const char*)Wh + (size_t)line * 128;
                asm volatile("prefetch.global.L2 [%0];" :: "l"(p));
            }
        } else if (pb < 16) {
            // W1: 256*64*4 = 65536 B = 512 lines; 2 blocks * 256 thr
            const int line = (pb - 14) * 256 + tid;
            if (line < 512) {
                const char* p = (const char*)W1 + (size_t)line * 128;
                asm volatile("prefetch.global.L2 [%0];" :: "l"(p));
            }
        } else {
            // bh: 7*256*4 = 7168 B = 56 lines
            if (tid < 56) {
                const char* p = (const char*)bh + (size_t)tid * 128;
                asm volatile("prefetch.global.L2 [%0];" :: "l"(p));
            }
        }
    }

    float acc = 0.0f;

    #pragma unroll
    for (int blk = 0; blk < NB0; ++blk) {
        const float4* row = reinterpret_cast<const float4*>(
            x0 + ((size_t)b * CH0 + (size_t)blk * BC + c) * TLEN);
        #pragma unroll
        for (int i = 0; i < 4; ++i) {
            float4 v = __ldcs(row + tid + i * 256);
            acc += (v.x + v.y) + (v.z + v.w);
        }
    }
    #pragma unroll
    for (int blk = 0; blk < NB1; ++blk) {
        const float4* row = reinterpret_cast<const float4*>(
            x1 + ((size_t)b * CH1 + (size_t)blk * BC + c) * TLEN);
        #pragma unroll
        for (int i = 0; i < 4; ++i) {
            float4 v = __ldcs(row + tid + i * 256);
            acc += (v.x + v.y) + (v.z + v.w);
        }
    }

    // Block reduction
    __shared__ float warpsum[8];
    #pragma unroll
    for (int o = 16; o > 0; o >>= 1)
        acc += __shfl_down_sync(0xffffffffu, acc, o);
    if ((tid & 31) == 0) warpsum[tid >> 5] = acc;
    __syncthreads();
    if (tid < 8) {
        float v = warpsum[tid];
        #pragma unroll
        for (int o = 4; o > 0; o >>= 1)
            v += __shfl_down_sync(0x000000ffu, v, o);
        if (tid == 0) g_gap[b * BC + c] = v * (1.0f / (float)TLEN);
    }
}

// ---------------------------------------------------------------------------
// Kernel 2 (fused): h = ReLU(BN(gap @ W1 + b1)) computed redundantly per block
// into smem, then scores = einsum('br,krc->kbc') + bh, softmax over k.
// 16 blocks x 128 threads; one thread per (b,c) pair. All weights L2-warm.
// ---------------------------------------------------------------------------
__global__ void __launch_bounds__(128) att_kernel(const float* __restrict__ W1,
                                                  const float* __restrict__ b1,
                                                  const float* __restrict__ gamma,
                                                  const float* __restrict__ beta,
                                                  const float* __restrict__ Wh,
                                                  const float* __restrict__ bh) {
    __shared__ float h_s[BATCH * RC];   // 512 floats
    const int tid = threadIdx.x;

    // --- compute h (redundant per block; trivial FLOPs, L2-warm weights) ---
    #pragma unroll
    for (int j = 0; j < 4; ++j) {
        const int o = tid + j * 128;         // 0..511
        const int b = o >> 6;
        const int r = o & (RC - 1);
        float s = b1[r];
        const float* gp = &g_gap[b * BC];
        #pragma unroll 8
        for (int c = 0; c < BC; ++c)
            s = fmaf(gp[c], W1[c * RC + r], s);
        const float bnscale = gamma[r] * rsqrtf(1.0f + 1e-5f);
        h_s[o] = fmaxf(fmaf(s, bnscale, beta[r]), 0.0f);
    }
    __syncthreads();

    // --- scores + softmax over k for this thread's (b,c) pair ---
    const int i = blockIdx.x * 128 + tid;    // 0..2047
    const int b = i >> 8;                    // / BC
    const int c = i & (BC - 1);
    const float* hb = &h_s[b * RC];

    float sc[TB];
    float mx = -1e30f;
    #pragma unroll
    for (int k = 0; k < TB; ++k) {
        float s = bh[k * BC + c];
        const float* w = Wh + (size_t)k * RC * BC + c;
        #pragma unroll 16
        for (int r = 0; r < RC; ++r)
            s = fmaf(hb[r], w[(size_t)r * BC], s);
        sc[k] = s;
        mx = fmaxf(mx, s);
    }
    float sum = 0.0f;
    #pragma unroll
    for (int k = 0; k < TB; ++k) { sc[k] = __expf(sc[k] - mx); sum += sc[k]; }
    const float inv = 1.0f / sum;
    #pragma unroll
    for (int k = 0; k < TB; ++k)
        g_att[(b * TB + k) * BC + c] = sc[k] * inv;
}

// ---------------------------------------------------------------------------
// Kernel 3: streaming scale. One block per channel-row (16 KB), float4 I/O,
// evict-first loads and stores (single-use data).
// ---------------------------------------------------------------------------
__global__ void __launch_bounds__(256) scale_kernel(const float* __restrict__ x0,
                                                    const float* __restrict__ x1,
                                                    float* __restrict__ out) {
    const int bid = blockIdx.x;
    const int tid = threadIdx.x;

    const float* src;
    float* dst;
    int b, ch, kblk;
    if (bid < BATCH * CH0) {
        b = bid >> 10;            // / CH0
        ch = bid & (CH0 - 1);
        src = x0 + (size_t)bid * TLEN;
        dst = out + (size_t)bid * TLEN;
        kblk = ch >> 8;
    } else {
        const int r = bid - BATCH * CH0;
        b = r / CH1;
        ch = r % CH1;
        src = x1 + (size_t)r * TLEN;
        dst = out + (size_t)BATCH * CH0 * TLEN + (size_t)r * TLEN;
        kblk = NB0 + (ch >> 8);
    }

    const float a = __ldg(&g_att[(b * TB + kblk) * BC + (ch & (BC - 1))]);

    const float4* s4 = reinterpret_cast<const float4*>(src);
    float4* d4 = reinterpret_cast<float4*>(dst);
    float4 v[4];
    #pragma unroll
    for (int i = 0; i < 4; ++i)
        v[i] = __ldcs(s4 + tid + i * 256);
    #pragma unroll
    for (int i = 0; i < 4; ++i) {
        v[i].x *= a; v[i].y *= a; v[i].z *= a; v[i].w *= a;
        __stcs(d4 + tid + i * 256, v[i]);
    }
}

// ---------------------------------------------------------------------------
extern "C" void kernel_launch(void* const* d_in, const int* in_sizes, int n_in,
                              void* d_out, int out_size) {
    const float* x0    = (const float*)d_in[0];  // [8,1024,4096]
    const float* x1    = (const float*)d_in[1];  // [8,768,4096]
    const float* W1    = (const float*)d_in[2];  // [256,64]
    const float* b1    = (const float*)d_in[3];  // [64]
    const float* gamma = (const float*)d_in[4];  // [64]
    const float* beta  = (const float*)d_in[5];  // [64]
    const float* Wh    = (const float*)d_in[6];  // [7,64,256]
    const float* bh    = (const float*)d_in[7];  // [7,256]
    float* out = (float*)d_out;

    gap_kernel<<<GAP_GRID, 256>>>(x0, x1, Wh, W1, bh);
    att_kernel<<<16, 128>>>(W1, b1, gamma, beta, Wh, bh);
    scale_kernel<<<BATCH * (CH0 + CH1), 256>>>(x0, x1, out);
}

// round 4
// speedup vs baseline: 1.3001x; 1.3001x over previous
#include <cuda_runtime.h>

// Problem constants (fixed shapes from reference)
#define BATCH 8
#define TLEN  4096
#define BC    256
#define RC    64
#define NB0   4
#define NB1   3
#define TB    7           // NB0 + NB1
#define CH0   1024        // x0 channels
#define CH1   768         // x1 channels

// Device-global scratch (allocation-free per harness rules)
__device__ float g_gap[BATCH * BC];
__device__ float g_scores[TB * BATCH * BC];   // [k][b][c]

// ---------------------------------------------------------------------------
// Kernel 1: block-sum over channel blocks + global average pool over time.
// grid = 2048 blocks, 256 threads. Streaming (evict-first) loads.
// ---------------------------------------------------------------------------
__global__ void __launch_bounds__(256) gap_kernel(const float* __restrict__ x0,
                                                  const float* __restrict__ x1) {
    const int b = blockIdx.x >> 8;      // / BC
    const int c = blockIdx.x & (BC - 1);
    const int tid = threadIdx.x;

    float acc = 0.0f;

    #pragma unroll
    for (int blk = 0; blk < NB0; ++blk) {
        const float4* row = reinterpret_cast<const float4*>(
            x0 + ((size_t)b * CH0 + (size_t)blk * BC + c) * TLEN);
        #pragma unroll
        for (int i = 0; i < 4; ++i) {
            float4 v = __ldcs(row + tid + i * 256);
            acc += (v.x + v.y) + (v.z + v.w);
        }
    }
    #pragma unroll
    for (int blk = 0; blk < NB1; ++blk) {
        const float4* row = reinterpret_cast<const float4*>(
            x1 + ((size_t)b * CH1 + (size_t)blk * BC + c) * TLEN);
        #pragma unroll
        for (int i = 0; i < 4; ++i) {
            float4 v = __ldcs(row + tid + i * 256);
            acc += (v.x + v.y) + (v.z + v.w);
        }
    }

    // Block reduction
    __shared__ float warpsum[8];
    #pragma unroll
    for (int o = 16; o > 0; o >>= 1)
        acc += __shfl_down_sync(0xffffffffu, acc, o);
    if ((tid & 31) == 0) warpsum[tid >> 5] = acc;
    __syncthreads();
    if (tid < 8) {
        float v = warpsum[tid];
        #pragma unroll
        for (int o = 4; o > 0; o >>= 1)
            v += __shfl_down_sync(0x000000ffu, v, o);
        if (tid == 0) g_gap[b * BC + c] = v * (1.0f / (float)TLEN);
    }
}

// ---------------------------------------------------------------------------
// Kernel 2: fused h + raw scores. grid = TB*BATCH (56) blocks x 256 threads.
// Block (k,b): compute h[b] (redundant across k, split-K over 256 threads,
// coalesced W1 reads), then score[k][b][c] with coalesced Wh reads.
// ---------------------------------------------------------------------------
__global__ void __launch_bounds__(256) score_kernel(const float* __restrict__ W1,
                                                    const float* __restrict__ b1,
                                                    const float* __restrict__ gamma,
                                                    const float* __restrict__ beta,
                                                    const float* __restrict__ Wh,
                                                    const float* __restrict__ bh) {
    const int k = blockIdx.x >> 3;       // / BATCH
    const int b = blockIdx.x & 7;
    const int tid = threadIdx.x;

    __shared__ float part[4][RC];        // split-K partials
    __shared__ float h_s[RC];

    // --- h[b] split-K: thread (s, r) accumulates over c in [s*64, s*64+64)
    {
        const int s = tid >> 6;          // 0..3
        const int r = tid & (RC - 1);    // 0..63
        const float* gp = &g_gap[b * BC + s * 64];
        const float* wp = W1 + (size_t)(s * 64) * RC + r;
        float acc = 0.0f;
        #pragma unroll 16
        for (int i = 0; i < 64; ++i)
            acc = fmaf(gp[i], wp[(size_t)i * RC], acc);   // coalesced: r varies
        part[s][r] = acc;
    }
    __syncthreads();
    if (tid < RC) {
        const int r = tid;
        float s = part[0][r] + part[1][r] + part[2][r] + part[3][r] + b1[r];
        const float bnscale = gamma[r] * rsqrtf(1.0f + 1e-5f);
        h_s[r] = fmaxf(fmaf(s, bnscale, beta[r]), 0.0f);
    }
    __syncthreads();

    // --- score[k][b][c], c = tid; Wh reads coalesced across c ---
    const int c = tid;
    float s = bh[k * BC + c];
    const float* w = Wh + (size_t)k * RC * BC + c;
    #pragma unroll 16
    for (int r = 0; r < RC; ++r)
        s = fmaf(h_s[r], w[(size_t)r * BC], s);
    g_scores[(k * BATCH + b) * BC + c] = s;
}

// ---------------------------------------------------------------------------
// Kernel 3: streaming scale with fused softmax. One block per channel-row
// (16 KB), float4 I/O, evict-first loads/stores. Each thread redundantly
// computes the softmax over k (7 broadcast loads + 7 exp, trivial).
// ---------------------------------------------------------------------------
__global__ void __launch_bounds__(256) scale_kernel(const float* __restrict__ x0,
                                                    const float* __restrict__ x1,
                                                    float* __restrict__ out) {
    const int bid = blockIdx.x;
    const int tid = threadIdx.x;

    const float* src;
    float* dst;
    int b, ch, kblk;
    if (bid < BATCH * CH0) {
        b = bid >> 10;            // / CH0
        ch = bid & (CH0 - 1);
        src = x0 + (size_t)bid * TLEN;
        dst = out + (size_t)bid * TLEN;
        kblk = ch >> 8;
    } else {
        const int r = bid - BATCH * CH0;
        b = r / CH1;
        ch = r % CH1;
        src = x1 + (size_t)r * TLEN;
        dst = out + (size_t)BATCH * CH0 * TLEN + (size_t)r * TLEN;
        kblk = NB0 + (ch >> 8);
    }
    const int c = ch & (BC - 1);

    // Fused softmax over k at (b,c): 7 uniform loads, L2-hot.
    float sc[TB];
    float mx = -1e30f;
    #pragma unroll
    for (int k = 0; k < TB; ++k) {
        sc[k] = __ldg(&g_scores[(k * BATCH + b) * BC + c]);
        mx = fmaxf(mx, sc[k]);
    }
    float sum = 0.0f;
    #pragma unroll
    for (int k = 0; k < TB; ++k) sum += __expf(sc[k] - mx);
    const float a = __expf(sc[kblk] - mx) / sum;

    const float4* s4 = reinterpret_cast<const float4*>(src);
    float4* d4 = reinterpret_cast<float4*>(dst);
    float4 v[4];
    #pragma unroll
    for (int i = 0; i < 4; ++i)
        v[i] = __ldcs(s4 + tid + i * 256);
    #pragma unroll
    for (int i = 0; i < 4; ++i) {
        v[i].x *= a; v[i].y *= a; v[i].z *= a; v[i].w *= a;
        __stcs(d4 + tid + i * 256, v[i]);
    }
}

// ---------------------------------------------------------------------------
extern "C" void kernel_launch(void* const* d_in, const int* in_sizes, int n_in,
                              void* d_out, int out_size) {
    const float* x0    = (const float*)d_in[0];  // [8,1024,4096]
    const float* x1    = (const float*)d_in[1];  // [8,768,4096]
    const float* W1    = (const float*)d_in[2];  // [256,64]
    const float* b1    = (const float*)d_in[3];  // [64]
    const float* gamma = (const float*)d_in[4];  // [64]
    const float* beta  = (const float*)d_in[5];  // [64]
    const float* Wh    = (const float*)d_in[6];  // [7,64,256]
    const float* bh    = (const float*)d_in[7];  // [7,256]
    float* out = (float*)d_out;

    gap_kernel<<<BATCH * BC, 256>>>(x0, x1);
    score_kernel<<<TB * BATCH, 256>>>(W1, b1, gamma, beta, Wh, bh);
    scale_kernel<<<BATCH * (CH0 + CH1), 256>>>(x0, x1, out);
}